// round 15
// baseline (speedup 1.0000x reference)
#include <cuda_runtime.h>

#define L     4096
#define TS    64                      // tile size
#define NT    (L / TS)                // 64 tiles
#define NBLK  (NT * (NT + 1) / 2)     // 2080 tile pairs (A <= B)
#define NTHR  256
#define SPAD  69                      // c2s row stride in floats (~2-way conflicts)

__device__ double g_clash = 0.0;
__device__ double g_p2    = 0.0;   // sum s*d^2   (masked: band removed)
__device__ double g_pd    = 0.0;   // sum s*d     (masked)
__device__ double g_cnm   = 0.0;   // sum s       (masked, for numerator)
__device__ double g_cnt   = 0.0;   // sum of ALL contact entries (n_pairs)
__device__ unsigned int g_done = 0;

__device__ __forceinline__ float fsqrt_approx(float x) {
    float r;
    asm("sqrt.approx.f32 %0, %1;" : "=f"(r) : "f"(x));
    return r;
}

__device__ __forceinline__ float warp_sum(float v) {
    v += __shfl_down_sync(0xffffffffu, v, 16);
    v += __shfl_down_sync(0xffffffffu, v, 8);
    v += __shfl_down_sync(0xffffffffu, v, 4);
    v += __shfl_down_sync(0xffffffffu, v, 2);
    v += __shfl_down_sync(0xffffffffu, v, 1);
    return v;
}

__device__ __forceinline__ void decode_pair(int k, int& A, int& B) {
    int a = (int)((129.0f - sqrtf(16641.0f - 8.0f * (float)k)) * 0.5f);
    while (64 * (a + 1) - (a + 1) * a / 2 <= k) ++a;
    while (64 * a - a * (a - 1) / 2 > k) --a;
    A = a;
    B = a + (k - (64 * a - a * (a - 1) / 2));
}

// Sweep a 4x4 subtile. DIAG masks to j > i inside the diagonal tile.
template <bool DIAG>
__device__ __forceinline__ void sweep(
    int ib, int jb, int ti, int tj,
    const float4* __restrict__ c1, const float4* __restrict__ pj,
    const float4* sA4, const float* c2s,
    float& cl0, float& cl1, float& p20, float& p21,
    float& pd0, float& pd1, float& cn0, float& cn1)
{
#pragma unroll
    for (int a = 0; a < 4; ++a) {
        const float4 pi = sA4[ti * 4 + a];          // broadcast LDS.128
        const float c1v[4] = {c1[a].x, c1[a].y, c1[a].z, c1[a].w};
#pragma unroll
        for (int b = 0; b < 4; ++b) {
            float cv2 = c2s[(tj * 4 + b) * SPAD + ti * 4 + a];
            float dx = pj[b].x - pi.x;
            float dy = pj[b].y - pi.y;
            float dz = pj[b].z - pi.z;
            float d2 = fmaf(dz, dz, fmaf(dy, dy, dx * dx));
            float d  = fsqrt_approx(d2);
            float t  = fmaxf(3.4f - d, 0.0f);
            float s  = c1v[b] + cv2;                // cv_ij + cv_ji
            if (DIAG) {
                float mask = (jb + b > ib + a) ? 1.0f : 0.0f;
                t *= mask;
                s *= mask;
            }
            // decomposed pair term: (d-9)^2 = d^2 - 18 d + 81
            if (b & 1) {
                cl1 = fmaf(t, t, cl1);
                p21 = fmaf(s, d2, p21);
                pd1 = fmaf(s, d, pd1);
                cn1 += s;
            } else {
                cl0 = fmaf(t, t, cl0);
                p20 = fmaf(s, d2, p20);
                pd0 = fmaf(s, d, pd0);
                cn0 += s;
            }
        }
    }
}

__global__ void __launch_bounds__(NTHR, 4)
energy_kernel(const float* __restrict__ coords,
              const float* __restrict__ cmap,
              float* __restrict__ out)
{
    __shared__ float4 sA4[TS], sB4[TS];      // {x,y,z,0} per residue
    __shared__ float  c2s[TS * SPAD];        // C2 tile rows (j'), padded stride
    __shared__ float  red[48];
    __shared__ float  flast;

    const int tid = threadIdx.x;

    int A, B;
    decode_pair((int)blockIdx.x, A, B);
    const bool diag = (A == B);
    const int i0 = A * TS;
    const int j0 = B * TS;

    // stage tile coords
    if (tid < TS) {
        sA4[tid] = make_float4(__ldg(coords + 3 * (i0 + tid) + 0),
                               __ldg(coords + 3 * (i0 + tid) + 1),
                               __ldg(coords + 3 * (i0 + tid) + 2), 0.0f);
    } else if (tid < 2 * TS) {
        const int t = tid - TS;
        sB4[t] = make_float4(__ldg(coords + 3 * (j0 + t) + 0),
                             __ldg(coords + 3 * (j0 + t) + 1),
                             __ldg(coords + 3 * (j0 + t) + 2), 0.0f);
    }

    const int ti = tid >> 4;                     // 0..15 -> 4 i-rows
    const int tj = tid & 15;                     // 0..15 -> 4 j-cols
    const int ib = i0 + ti * 4;
    const int jb = j0 + tj * 4;

    // front-load: c2 tile (4 LDG.128) then c1 sub-rows (4 LDG.128), STS last
    float4 t2[4];
#pragma unroll
    for (int m = 0; m < 4; ++m) {
        const int s = tid + m * NTHR;
        t2[m] = __ldg(((const float4*)(cmap + (size_t)(j0 + (s >> 4)) * L + i0)) + (s & 15));
    }
    float4 c1[4];
#pragma unroll
    for (int r = 0; r < 4; ++r)
        c1[r] = __ldg(((const float4*)(cmap + (size_t)(ib + r) * L + j0)) + tj);
#pragma unroll
    for (int m = 0; m < 4; ++m) {
        const int s = tid + m * NTHR;
        float* dst = &c2s[(s >> 4) * SPAD + (s & 15) * 4];
        dst[0] = t2[m].x; dst[1] = t2[m].y; dst[2] = t2[m].z; dst[3] = t2[m].w;
    }
    __syncthreads();

    float4 pj[4];
#pragma unroll
    for (int b = 0; b < 4; ++b) pj[b] = sB4[tj * 4 + b];

    float cl0 = 0.f, cl1 = 0.f, p20 = 0.f, p21 = 0.f;
    float pd0 = 0.f, pd1 = 0.f, cn0 = 0.f, cn1 = 0.f;
    if (diag) sweep<true >(ib, jb, ti, tj, c1, pj, sA4, c2s, cl0, cl1, p20, p21, pd0, pd1, cn0, cn1);
    else      sweep<false>(ib, jb, ti, tj, c1, pj, sA4, c2s, cl0, cl1, p20, p21, pd0, pd1, cn0, cn1);

    float aclash = cl0 + cl1;
    float ap2    = p20 + p21;
    float apd    = pd0 + pd1;
    float acn    = cn0 + cn1;
    float acnt   = acn;     // ALL contact entries (denominator); band stays
    float acnm   = acn;     // masked count (numerator); band removed below

    // diag blocks: count diagonal c_ii (denominator only) and remove band
    // pairs j-i in {1,2} from clash + pair numerator (same fp expressions)
    if (diag) {
        if (tid < TS)
            acnt += __ldg(cmap + (size_t)(i0 + tid) * L + (i0 + tid));
        if (tid < 2 * TS) {
            const int o = 1 + (tid >> 6);        // 1 or 2
            const int i = i0 + (tid & 63);
            const int j = i + o;
            if (j < L) {
                float xi = __ldg(coords + 3 * i + 0);
                float yi = __ldg(coords + 3 * i + 1);
                float zi = __ldg(coords + 3 * i + 2);
                float xJ = __ldg(coords + 3 * j + 0);
                float yJ = __ldg(coords + 3 * j + 1);
                float zJ = __ldg(coords + 3 * j + 2);
                float dx = xJ - xi, dy = yJ - yi, dz = zJ - zi;
                float d2 = fmaf(dz, dz, fmaf(dy, dy, dx * dx));
                float d  = fsqrt_approx(d2);
                float t  = fmaxf(3.4f - d, 0.0f);
                aclash   = fmaf(-t, t, aclash);
                float s  = __ldg(cmap + (size_t)i * L + j) + __ldg(cmap + (size_t)j * L + i);
                ap2  = fmaf(-s, d2, ap2);
                apd  = fmaf(-s, d, apd);
                acnm -= s;
                // band contacts remain in acnt (reference counts them in n_pairs)
            }
        }
    }

    // block reduction (8 warps, 5 quantities)
    aclash = warp_sum(aclash);
    ap2    = warp_sum(ap2);
    apd    = warp_sum(apd);
    acnm   = warp_sum(acnm);
    acnt   = warp_sum(acnt);
    const int wid  = tid >> 5;
    const int lane = tid & 31;
    if (lane == 0) {
        red[wid]          = aclash;
        red[8 + wid]      = ap2;
        red[16 + wid]     = apd;
        red[24 + wid]     = acnm;
        red[32 + wid]     = acnt;
    }
    __syncthreads();
    if (tid == 0) {
        float s0 = 0.f, s1 = 0.f, s2 = 0.f, s3 = 0.f, s4 = 0.f;
        for (int w = 0; w < 8; ++w) {
            s0 += red[w];      s1 += red[8 + w];  s2 += red[16 + w];
            s3 += red[24 + w]; s4 += red[32 + w];
        }
        atomicAdd(&g_clash, (double)s0);
        atomicAdd(&g_p2,    (double)s1);
        atomicAdd(&g_pd,    (double)s2);
        atomicAdd(&g_cnm,   (double)s3);
        atomicAdd(&g_cnt,   (double)s4);
        __threadfence();
        unsigned prev = atomicAdd(&g_done, 1u);
        flast = (prev == (unsigned)(NBLK - 1)) ? 1.0f : 0.0f;
    }
    __syncthreads();

    // last block: bond term + finalize + reset for next graph replay
    if (flast != 0.0f) {
        float b = 0.0f;
        for (int k2 = tid; k2 < L - 1; k2 += NTHR) {
            float dx = __ldg(coords + 3 * k2 + 3) - __ldg(coords + 3 * k2 + 0);
            float dy = __ldg(coords + 3 * k2 + 4) - __ldg(coords + 3 * k2 + 1);
            float dz = __ldg(coords + 3 * k2 + 5) - __ldg(coords + 3 * k2 + 2);
            float d  = fsqrt_approx(fmaf(dz, dz, fmaf(dy, dy, dx * dx)));
            float t  = d - 6.0f;                 // IDEAL_C1_C1
            b = fmaf(t, t, b);
        }
        b = warp_sum(b);
        __syncthreads();
        if (lane == 0) red[wid] = b;
        __syncthreads();
        if (tid == 0) {
            float bs = 0.0f;
            for (int w = 0; w < 8; ++w) bs += red[w];
            double e_bond  = (double)bs / (double)(L - 1);
            double e_clash = g_clash / (double)L;    // unordered j>=i+3, counted once
            double cnt     = g_cnt < 1.0 ? 1.0 : g_cnt;
            // sum s*(d-9)^2 = p2 - 18*pd + 81*cnm over masked pairs
            double num     = g_p2 - 18.0 * g_pd + 81.0 * g_cnm;
            double e_pair  = num / cnt;
            out[0] = (float)(e_bond + 2.0 * e_clash + 0.5 * e_pair);
            g_clash = 0.0;
            g_p2    = 0.0;
            g_pd    = 0.0;
            g_cnm   = 0.0;
            g_cnt   = 0.0;
            g_done  = 0u;
        }
    }
}

extern "C" void kernel_launch(void* const* d_in, const int* in_sizes, int n_in,
                              void* d_out, int out_size) {
    const float* a0 = (const float*)d_in[0];
    const float* a1 = (const float*)d_in[1];
    // coords is the small input (L*3), contact_map the big one (L*L)
    const float* coords = (in_sizes[0] < in_sizes[1]) ? a0 : a1;
    const float* cmap   = (in_sizes[0] < in_sizes[1]) ? a1 : a0;
    energy_kernel<<<NBLK, NTHR>>>(coords, cmap, (float*)d_out);
}